// round 1
// baseline (speedup 1.0000x reference)
#include <cuda_runtime.h>
#include <cstdint>

#define NTOK 32768
#define HDIM 768
#define NEXP 8
#define KTOP 2
#define TM 128
#define TN 128
#define TK 8
#define KITERS (HDIM / TK)          // 96
#define LDP 10                       // padded smem row stride (words); keeps u64 8B-aligned, conflict-free
#define MAXTILES (NTOK / TM + NEXP)  // 264 >= sum ceil(n_e/128)

typedef unsigned long long u64;

// ---------------- scratch (device globals; no allocation allowed) ----------------
__device__ int   g_eid[2][NTOK];
__device__ float g_wt [2][NTOK];
__device__ int   g_cnt[2][NEXP];
__device__ int   g_cur[2][NEXP];
__device__ int   g_off[2][NEXP + 1];
__device__ int   g_ts [2][NEXP + 1];
__device__ int   g_bucket[2][NTOK];
__device__ float g_bw[2][NTOK];

// ---------------- small helpers ----------------
__device__ __forceinline__ void ffma2(u64 &d, u64 a, u64 b) {
    asm("fma.rn.f32x2 %0, %1, %2, %0;" : "+l"(d) : "l"(a), "l"(b));
}
__device__ __forceinline__ void cpa8(uint32_t s, const float* g) {
    asm volatile("cp.async.ca.shared.global [%0], [%1], 8;" :: "r"(s), "l"(g));
}
__device__ __forceinline__ void cp_commit() { asm volatile("cp.async.commit_group;"); }
template <int N> __device__ __forceinline__ void cp_wait() {
    asm volatile("cp.async.wait_group %0;" :: "n"(N));
}

// ---------------- kernel 0: zero counters (graph replays need fresh state) ----------------
__global__ void init_kernel() {
    int t = threadIdx.x;
    if (t < 2 * NEXP) {
        ((int*)g_cnt)[t] = 0;
        ((int*)g_cur)[t] = 0;
    }
}

// ---------------- kernel 1: router (1 warp per token) ----------------
__global__ __launch_bounds__(256) void router_kernel(
    const float* __restrict__ x, const float* __restrict__ rw, const float* __restrict__ rb)
{
    __shared__ float s_rw[NEXP * HDIM];
    for (int i = threadIdx.x; i < NEXP * HDIM; i += 256) s_rw[i] = rw[i];
    __syncthreads();

    int warp = threadIdx.x >> 5, lane = threadIdx.x & 31;
    int tok = (blockIdx.x << 3) + warp;   // grid 4096 * 8 warps = 32768, always valid
    const float* xr = x + (size_t)tok * HDIM;

    float acc[NEXP];
#pragma unroll
    for (int e = 0; e < NEXP; e++) acc[e] = 0.f;

#pragma unroll 4
    for (int i = 0; i < HDIM / 32; i++) {
        float xv = xr[i * 32 + lane];
#pragma unroll
        for (int e = 0; e < NEXP; e++)
            acc[e] = fmaf(xv, s_rw[e * HDIM + i * 32 + lane], acc[e]);
    }
#pragma unroll
    for (int e = 0; e < NEXP; e++) {
#pragma unroll
        for (int o = 16; o > 0; o >>= 1)
            acc[e] += __shfl_xor_sync(0xffffffffu, acc[e], o);
    }

    if (lane == 0) {
        float s[NEXP];
#pragma unroll
        for (int e = 0; e < NEXP; e++) s[e] = acc[e] + rb[e];
        float m = s[0];
#pragma unroll
        for (int e = 1; e < NEXP; e++) m = fmaxf(m, s[e]);
        float p[NEXP]; float Z = 0.f;
#pragma unroll
        for (int e = 0; e < NEXP; e++) { p[e] = expf(s[e] - m); Z += p[e]; }
        // top-2 (first-index tie-break, matching lax.top_k)
        int e0 = 0;
#pragma unroll
        for (int e = 1; e < NEXP; e++) if (p[e] > p[e0]) e0 = e;
        int e1 = (e0 == 0) ? 1 : 0;
#pragma unroll
        for (int e = 0; e < NEXP; e++) if (e != e0 && p[e] > p[e1]) e1 = e;
        float p0 = p[e0] / Z, p1 = p[e1] / Z;
        float inv = 1.f / (p0 + p1 + 1e-9f);
        g_eid[0][tok] = e0; g_wt[0][tok] = p0 * inv;
        g_eid[1][tok] = e1; g_wt[1][tok] = p1 * inv;
        atomicAdd(&g_cnt[0][e0], 1);
        atomicAdd(&g_cnt[1][e1], 1);
    }
}

// ---------------- kernel 2: scan (tiny, 1 thread) ----------------
__global__ void scan_kernel() {
    if (threadIdx.x == 0 && blockIdx.x == 0) {
        for (int s = 0; s < 2; s++) {
            int o = 0, t = 0;
            for (int e = 0; e < NEXP; e++) {
                g_off[s][e] = o;
                g_ts [s][e] = t;
                o += g_cnt[s][e];
                t += (g_cnt[s][e] + TM - 1) >> 7;
            }
            g_off[s][NEXP] = o;
            g_ts [s][NEXP] = t;
        }
    }
}

// ---------------- kernel 3: scatter tokens into per-(slot,expert) buckets ----------------
__global__ __launch_bounds__(256) void scatter_kernel() {
    int t = blockIdx.x * 256 + threadIdx.x;
    if (t >= NTOK) return;
#pragma unroll
    for (int s = 0; s < 2; s++) {
        int e = g_eid[s][t];
        int pos = g_off[s][e] + atomicAdd(&g_cur[s][e], 1);
        g_bucket[s][pos] = t;
        g_bw[s][pos] = g_wt[s][t];
    }
}

// ---------------- kernel 4: grouped GEMM, fp32 with fma.rn.f32x2 (k-paired) ----------------
// out[tok, n] (=/+=) w_tok * ( sum_h x[tok,h] * W[e,n,h] + b[e,n] )
template <int SLOT, bool ACC>
__global__ __launch_bounds__(256, 1) void moe_gemm(
    const float* __restrict__ x, const float* __restrict__ ew,
    const float* __restrict__ eb, float* __restrict__ out)
{
    __shared__ __align__(16) float sA[2][TM * LDP];
    __shared__ __align__(16) float sB[2][TN * LDP];
    __shared__ int   sTok[TM];
    __shared__ float sW[TM];
    __shared__ float sBias[TN];
    __shared__ int   sMeta[3];

    int tid = threadIdx.x;
    if (tid == 0) {
        int bx = blockIdx.x;
        if (bx >= g_ts[SLOT][NEXP]) {
            sMeta[0] = -1;
        } else {
            int e = 0;
            while (g_ts[SLOT][e + 1] <= bx) e++;
            sMeta[0] = e;
            sMeta[1] = g_off[SLOT][e] + ((bx - g_ts[SLOT][e]) << 7);  // m0 (bucket pos)
            sMeta[2] = g_off[SLOT][e + 1];                             // mEnd
        }
    }
    __syncthreads();
    int e = sMeta[0];
    if (e < 0) return;
    int m0 = sMeta[1], mEnd = sMeta[2];
    int nBase = blockIdx.y << 7;

    if (tid < TM) {
        int p = m0 + tid;
        int pc = p < NTOK ? p : NTOK - 1;  // clamp: safe read; store is guarded by mEnd
        sTok[tid] = g_bucket[SLOT][pc];
        sW[tid]   = g_bw[SLOT][pc];
        sBias[tid] = eb[e * HDIM + nBase + tid];
    }
    __syncthreads();

    int tx = tid & 15, ty = tid >> 4;      // micro-tile coords (strided mapping)
    int r = tid >> 1, q = tid & 1;         // tile-load coords: row r, half q

    const float* gA = x + (size_t)sTok[r] * HDIM + q * 4;
    const float* gB = ew + ((size_t)e * HDIM + nBase + r) * HDIM + q * 4;
    uint32_t saA = (uint32_t)__cvta_generic_to_shared(&sA[0][r * LDP + q * 4]);
    uint32_t saB = (uint32_t)__cvta_generic_to_shared(&sB[0][r * LDP + q * 4]);
    const uint32_t bufStride = TM * LDP * 4;

    // prefetch k-tile 0 -> buf 0
    cpa8(saA, gA);     cpa8(saA + 8, gA + 2);
    cpa8(saB, gB);     cpa8(saB + 8, gB + 2);
    cp_commit();

    u64 acc[8][8];
#pragma unroll
    for (int i = 0; i < 8; i++)
#pragma unroll
        for (int j = 0; j < 8; j++) acc[i][j] = 0ull;

    for (int kt = 0; kt < KITERS; kt++) {
        int buf = kt & 1;
        if (kt + 1 < KITERS) {
            const float* a = gA + (kt + 1) * TK;
            const float* b = gB + (kt + 1) * TK;
            uint32_t oA = saA + (uint32_t)(buf ^ 1) * bufStride;
            uint32_t oB = saB + (uint32_t)(buf ^ 1) * bufStride;
            cpa8(oA, a);     cpa8(oA + 8, a + 2);
            cpa8(oB, b);     cpa8(oB + 8, b + 2);
        }
        cp_commit();
        cp_wait<1>();       // tile kt complete (only the kt+1 group may be in flight)
        __syncthreads();

        const float* A = sA[buf];
        const float* B = sB[buf];
#pragma unroll
        for (int kp = 0; kp < TK / 2; kp++) {
            u64 aP[8], bP[8];
#pragma unroll
            for (int i = 0; i < 8; i++)
                aP[i] = *(const u64*)(A + (ty + 16 * i) * LDP + 2 * kp);
#pragma unroll
            for (int j = 0; j < 8; j++)
                bP[j] = *(const u64*)(B + (tx + 16 * j) * LDP + 2 * kp);
#pragma unroll
            for (int i = 0; i < 8; i++)
#pragma unroll
                for (int j = 0; j < 8; j++)
                    ffma2(acc[i][j], aP[i], bP[j]);
        }
        __syncthreads();
    }

    // epilogue: lo+hi (even/odd-k partials), + bias, * gate weight, scatter to out rows
#pragma unroll
    for (int i = 0; i < 8; i++) {
        int m = ty + 16 * i;
        if (m0 + m >= mEnd) continue;
        float wgt = sW[m];
        float* orow = out + (size_t)sTok[m] * HDIM + nBase;
#pragma unroll
        for (int j = 0; j < 8; j++) {
            int n = tx + 16 * j;
            float lo, hi;
            asm("mov.b64 {%0, %1}, %2;" : "=f"(lo), "=f"(hi) : "l"(acc[i][j]));
            float v = wgt * (lo + hi + sBias[n]);
            if (ACC) orow[n] += v;
            else     orow[n] = v;
        }
    }
}

// ---------------- launch ----------------
extern "C" void kernel_launch(void* const* d_in, const int* in_sizes, int n_in,
                              void* d_out, int out_size)
{
    const float* x  = (const float*)d_in[0];
    const float* rw = (const float*)d_in[1];
    const float* rb = (const float*)d_in[2];
    const float* ew = (const float*)d_in[3];
    const float* eb = (const float*)d_in[4];
    float* out = (float*)d_out;
    (void)in_sizes; (void)n_in; (void)out_size;

    init_kernel<<<1, 32>>>();
    router_kernel<<<NTOK / 8, 256>>>(x, rw, rb);
    scan_kernel<<<1, 32>>>();
    scatter_kernel<<<NTOK / 256, 256>>>();
    moe_gemm<0, false><<<dim3(MAXTILES, HDIM / TN), 256>>>(x, ew, eb, out);
    moe_gemm<1, true ><<<dim3(MAXTILES, HDIM / TN), 256>>>(x, ew, eb, out);
}

// round 3
// speedup vs baseline: 2.1935x; 2.1935x over previous
#include <cuda_runtime.h>
#include <cuda_fp16.h>
#include <cstdint>

#define NTOK 32768
#define HDIM 768
#define NEXP 8
#define TM 128
#define MAXTILES (NTOK / TM + NEXP)  // 264

// GEMM tiles
#define CTM 128
#define CTN 128
#define CTK 32                        // halves per k-stage
#define KT  (HDIM / CTK)              // 24 stages
#define NSTG 3
#define ROWB 80                       // padded row stride bytes (32 halves + 8 pad)
#define ROWW 20                       // row stride in words
#define TILEB (128 * ROWB)            // 10240 bytes per (128 x 32) half tile
#define STAGEB (4 * TILEB)            // Ah, Al, Bh, Bl
#define SMEM_BYTES (NSTG * STAGEB)    // 122880

typedef unsigned long long u64;

// ---------------- scratch ----------------
__device__ int   g_eid[2][NTOK];
__device__ float g_wt [2][NTOK];
__device__ int   g_cnt[2][NEXP];
__device__ int   g_cur[2][NEXP];
__device__ int   g_off[2][NEXP + 1];
__device__ int   g_ts [2][NEXP + 1];
__device__ int   g_bucket[2][NTOK];
__device__ float g_bw[2][NTOK];

__device__ __half g_xh[NTOK * HDIM];
__device__ __half g_xl[NTOK * HDIM];
__device__ __half g_wh[NEXP * HDIM * HDIM];
__device__ __half g_wl[NEXP * HDIM * HDIM];

// ---------------- helpers ----------------
__device__ __forceinline__ void cpa16(uint32_t s, const void* g) {
    asm volatile("cp.async.cg.shared.global [%0], [%1], 16;" :: "r"(s), "l"(g));
}
__device__ __forceinline__ void cp_commit() { asm volatile("cp.async.commit_group;"); }
template <int N> __device__ __forceinline__ void cp_wait() {
    asm volatile("cp.async.wait_group %0;" :: "n"(N));
}
__device__ __forceinline__ void mma16816(float* c, const uint32_t* a, const uint32_t* b) {
    asm volatile(
        "mma.sync.aligned.m16n8k16.row.col.f32.f16.f16.f32 "
        "{%0,%1,%2,%3}, {%4,%5,%6,%7}, {%8,%9}, {%0,%1,%2,%3};"
        : "+f"(c[0]), "+f"(c[1]), "+f"(c[2]), "+f"(c[3])
        : "r"(a[0]), "r"(a[1]), "r"(a[2]), "r"(a[3]), "r"(b[0]), "r"(b[1]));
}

// ---------------- kernel 0: zero counters ----------------
__global__ void init_kernel() {
    int t = threadIdx.x;
    if (t < 2 * NEXP) { ((int*)g_cnt)[t] = 0; ((int*)g_cur)[t] = 0; }
}

// ---------------- convert kernels (fp32 -> fp16 hi/lo) ----------------
__global__ __launch_bounds__(256) void convx_kernel(const float* __restrict__ x) {
    int i = blockIdx.x * 256 + threadIdx.x;
    float v = x[i];
    __half h = __float2half(v);
    g_xh[i] = h;
    g_xl[i] = __float2half(v - __half2float(h));
}
__global__ __launch_bounds__(256) void convw_kernel(const float* __restrict__ w) {
    int i = blockIdx.x * 256 + threadIdx.x;
    float v = w[i];
    __half h = __float2half(v);
    g_wh[i] = h;
    g_wl[i] = __float2half(v - __half2float(h));
}

// ---------------- kernel 1: router ----------------
__global__ __launch_bounds__(256) void router_kernel(
    const float* __restrict__ x, const float* __restrict__ rw, const float* __restrict__ rb)
{
    __shared__ float s_rw[NEXP * HDIM];
    for (int i = threadIdx.x; i < NEXP * HDIM; i += 256) s_rw[i] = rw[i];
    __syncthreads();

    int warp = threadIdx.x >> 5, lane = threadIdx.x & 31;
    int tok = (blockIdx.x << 3) + warp;
    const float* xr = x + (size_t)tok * HDIM;

    float acc[NEXP];
#pragma unroll
    for (int e = 0; e < NEXP; e++) acc[e] = 0.f;
#pragma unroll 4
    for (int i = 0; i < HDIM / 32; i++) {
        float xv = xr[i * 32 + lane];
#pragma unroll
        for (int e = 0; e < NEXP; e++)
            acc[e] = fmaf(xv, s_rw[e * HDIM + i * 32 + lane], acc[e]);
    }
#pragma unroll
    for (int e = 0; e < NEXP; e++)
#pragma unroll
        for (int o = 16; o > 0; o >>= 1)
            acc[e] += __shfl_xor_sync(0xffffffffu, acc[e], o);

    if (lane == 0) {
        float s[NEXP];
#pragma unroll
        for (int e = 0; e < NEXP; e++) s[e] = acc[e] + rb[e];
        float m = s[0];
#pragma unroll
        for (int e = 1; e < NEXP; e++) m = fmaxf(m, s[e]);
        float p[NEXP]; float Z = 0.f;
#pragma unroll
        for (int e = 0; e < NEXP; e++) { p[e] = expf(s[e] - m); Z += p[e]; }
        int e0 = 0;
#pragma unroll
        for (int e = 1; e < NEXP; e++) if (p[e] > p[e0]) e0 = e;
        int e1 = (e0 == 0) ? 1 : 0;
#pragma unroll
        for (int e = 0; e < NEXP; e++) if (e != e0 && p[e] > p[e1]) e1 = e;
        float p0 = p[e0] / Z, p1 = p[e1] / Z;
        float inv = 1.f / (p0 + p1 + 1e-9f);
        g_eid[0][tok] = e0; g_wt[0][tok] = p0 * inv;
        g_eid[1][tok] = e1; g_wt[1][tok] = p1 * inv;
        atomicAdd(&g_cnt[0][e0], 1);
        atomicAdd(&g_cnt[1][e1], 1);
    }
}

// ---------------- kernel 2: scan ----------------
__global__ void scan_kernel() {
    if (threadIdx.x == 0 && blockIdx.x == 0) {
        for (int s = 0; s < 2; s++) {
            int o = 0, t = 0;
            for (int e = 0; e < NEXP; e++) {
                g_off[s][e] = o; g_ts[s][e] = t;
                o += g_cnt[s][e];
                t += (g_cnt[s][e] + TM - 1) >> 7;
            }
            g_off[s][NEXP] = o; g_ts[s][NEXP] = t;
        }
    }
}

// ---------------- kernel 3: scatter ----------------
__global__ __launch_bounds__(256) void scatter_kernel() {
    int t = blockIdx.x * 256 + threadIdx.x;
    if (t >= NTOK) return;
#pragma unroll
    for (int s = 0; s < 2; s++) {
        int e = g_eid[s][t];
        int pos = g_off[s][e] + atomicAdd(&g_cur[s][e], 1);
        g_bucket[s][pos] = t;
        g_bw[s][pos] = g_wt[s][t];
    }
}

// ---------------- kernel 4: grouped GEMM via mma.sync (fp16 hi/lo) ----------------
template <int SLOT, bool ACC>
__global__ __launch_bounds__(256, 1)
void moe_mma(const float* __restrict__ eb, float* __restrict__ out)
{
    extern __shared__ __align__(128) char smem[];
    const uint32_t sb = (uint32_t)__cvta_generic_to_shared(smem);

    __shared__ int   sMeta[3];
    __shared__ int   sTok[CTM];
    __shared__ float sWgt[CTM];
    __shared__ float sBias[CTN];

    int tid = threadIdx.x;
    int wid = tid >> 5, lane = tid & 31;

    if (tid == 0) {
        int bx = blockIdx.x;
        if (bx >= g_ts[SLOT][NEXP]) sMeta[0] = -1;
        else {
            int e = 0;
            while (g_ts[SLOT][e + 1] <= bx) e++;
            sMeta[0] = e;
            sMeta[1] = g_off[SLOT][e] + ((bx - g_ts[SLOT][e]) << 7);
            sMeta[2] = g_off[SLOT][e + 1];
        }
    }
    __syncthreads();
    int e = sMeta[0];
    if (e < 0) return;
    int m0 = sMeta[1], mEnd = sMeta[2];
    int nBase = blockIdx.y << 7;   // * 128

    if (tid < CTM) {
        int p = m0 + tid;
        int pc = p < mEnd ? p : mEnd - 1;
        sTok[tid] = g_bucket[SLOT][pc];
        sWgt[tid] = g_bw[SLOT][pc];
        sBias[tid] = eb[e * HDIM + nBase + tid];
    }
    __syncthreads();

    // ---- stage loader: 8 cp.async(16B) per thread ----
    int lrow = tid >> 1;                 // 0..127
    int lc0  = (tid & 1) * 2;            // chunk 0 or 2
    size_t gAr = (size_t)sTok[lrow] * HDIM;
    size_t gBr = ((size_t)e * HDIM + nBase + lrow) * HDIM;

    auto load_stage = [&](int kt, int buf) {
        uint32_t sbase = sb + (uint32_t)buf * STAGEB;
        int kc = kt * CTK;
#pragma unroll
        for (int t = 0; t < 2; t++) {
            int c = lc0 + t;
            uint32_t so = (uint32_t)(lrow * ROWB + c * 16);
            size_t gA = gAr + kc + c * 8;
            size_t gB = gBr + kc + c * 8;
            cpa16(sbase + 0 * TILEB + so, g_xh + gA);
            cpa16(sbase + 1 * TILEB + so, g_xl + gA);
            cpa16(sbase + 2 * TILEB + so, g_wh + gB);
            cpa16(sbase + 3 * TILEB + so, g_wl + gB);
        }
    };

    load_stage(0, 0); cp_commit();
    load_stage(1, 1); cp_commit();
    load_stage(2, 2); cp_commit();

    int warp_m = wid >> 1, warp_n = wid & 1;
    int r = lane >> 2, q = lane & 3;

    float acc[2][8][4];
#pragma unroll
    for (int mt = 0; mt < 2; mt++)
#pragma unroll
        for (int nt = 0; nt < 8; nt++)
#pragma unroll
            for (int i = 0; i < 4; i++) acc[mt][nt][i] = 0.f;

    for (int kt = 0; kt < KT; kt++) {
        int buf = kt % NSTG;
        if (kt < KT - 2) cp_wait<2>();
        else if (kt == KT - 2) cp_wait<1>();
        else cp_wait<0>();
        __syncthreads();

        const uint32_t* sAh = (const uint32_t*)(smem + buf * STAGEB);
        const uint32_t* sAl = (const uint32_t*)(smem + buf * STAGEB + TILEB);
        const uint32_t* sBh = (const uint32_t*)(smem + buf * STAGEB + 2 * TILEB);
        const uint32_t* sBl = (const uint32_t*)(smem + buf * STAGEB + 3 * TILEB);

#pragma unroll
        for (int k16 = 0; k16 < 2; k16++) {
            uint32_t ah[2][4], al[2][4], bh[8][2], bl[8][2];
#pragma unroll
            for (int mt = 0; mt < 2; mt++) {
                int w = (warp_m * 32 + mt * 16 + r) * ROWW + k16 * 8 + q;
                ah[mt][0] = sAh[w];            ah[mt][1] = sAh[w + 8 * ROWW];
                ah[mt][2] = sAh[w + 4];        ah[mt][3] = sAh[w + 8 * ROWW + 4];
                al[mt][0] = sAl[w];            al[mt][1] = sAl[w + 8 * ROWW];
                al[mt][2] = sAl[w + 4];        al[mt][3] = sAl[w + 8 * ROWW + 4];
            }
#pragma unroll
            for (int nt = 0; nt < 8; nt++) {
                int w = (warp_n * 64 + nt * 8 + r) * ROWW + k16 * 8 + q;
                bh[nt][0] = sBh[w];            bh[nt][1] = sBh[w + 4];
                bl[nt][0] = sBl[w];            bl[nt][1] = sBl[w + 4];
            }
#pragma unroll
            for (int mt = 0; mt < 2; mt++)
#pragma unroll
                for (int nt = 0; nt < 8; nt++) {
                    mma16816(acc[mt][nt], ah[mt], bh[nt]);
                    mma16816(acc[mt][nt], ah[mt], bl[nt]);
                    mma16816(acc[mt][nt], al[mt], bh[nt]);
                }
        }
        __syncthreads();
        if (kt + NSTG < KT) { load_stage(kt + NSTG, buf); cp_commit(); }
    }

    // ---- epilogue ----
#pragma unroll
    for (int mt = 0; mt < 2; mt++) {
        int lr0 = warp_m * 32 + mt * 16 + r;
        int lr1 = lr0 + 8;
        bool v0 = (m0 + lr0) < mEnd;
        bool v1 = (m0 + lr1) < mEnd;
        float w0 = sWgt[lr0], w1 = sWgt[lr1];
        float* o0 = out + (size_t)sTok[lr0] * HDIM + nBase;
        float* o1 = out + (size_t)sTok[lr1] * HDIM + nBase;
#pragma unroll
        for (int nt = 0; nt < 8; nt++) {
            int lc = warp_n * 64 + nt * 8 + 2 * q;
            float bx = sBias[lc], by = sBias[lc + 1];
            if (v0) {
                float2 v;
                v.x = w0 * (acc[mt][nt][0] + bx);
                v.y = w0 * (acc[mt][nt][1] + by);
                float2* dst = (float2*)(o0 + lc);
                if (ACC) { float2 o = *dst; o.x += v.x; o.y += v.y; *dst = o; }
                else *dst = v;
            }
            if (v1) {
                float2 v;
                v.x = w1 * (acc[mt][nt][2] + bx);
                v.y = w1 * (acc[mt][nt][3] + by);
                float2* dst = (float2*)(o1 + lc);
                if (ACC) { float2 o = *dst; o.x += v.x; o.y += v.y; *dst = o; }
                else *dst = v;
            }
        }
    }
}

// ---------------- launch ----------------
extern "C" void kernel_launch(void* const* d_in, const int* in_sizes, int n_in,
                              void* d_out, int out_size)
{
    const float* x  = (const float*)d_in[0];
    const float* rw = (const float*)d_in[1];
    const float* rb = (const float*)d_in[2];
    const float* ew = (const float*)d_in[3];
    const float* eb = (const float*)d_in[4];
    float* out = (float*)d_out;
    (void)in_sizes; (void)n_in; (void)out_size;

    cudaFuncSetAttribute(moe_mma<0, false>, cudaFuncAttributeMaxDynamicSharedMemorySize, SMEM_BYTES);
    cudaFuncSetAttribute(moe_mma<1, true >, cudaFuncAttributeMaxDynamicSharedMemorySize, SMEM_BYTES);

    init_kernel<<<1, 32>>>();
    convx_kernel<<<NTOK * HDIM / 256, 256>>>(x);
    convw_kernel<<<NEXP * HDIM * HDIM / 256, 256>>>(ew);
    router_kernel<<<NTOK / 8, 256>>>(x, rw, rb);
    scan_kernel<<<1, 32>>>();
    scatter_kernel<<<NTOK / 256, 256>>>();
    moe_mma<0, false><<<dim3(MAXTILES, HDIM / CTN), 256, SMEM_BYTES>>>(eb, out);
    moe_mma<1, true ><<<dim3(MAXTILES, HDIM / CTN), 256, SMEM_BYTES>>>(eb, out);
}

// round 4
// speedup vs baseline: 2.3346x; 1.0643x over previous
#include <cuda_runtime.h>
#include <cuda_fp16.h>
#include <cstdint>

#define NTOK 32768
#define HDIM 768
#define NEXP 8
#define TM 128
#define MAXTILES (NTOK / TM + NEXP)  // 264

// GEMM tiles
#define CTM 128
#define CTN 128
#define CTK 32                        // halves per k-stage
#define KT  (HDIM / CTK)              // 24 stages
#define NSTG 3
#define ROWB 80                       // padded row stride bytes (32 halves + 8 pad)
#define TILEB (128 * ROWB)            // 10240 bytes per (128 x 32) half tile
#define STAGEB (4 * TILEB)            // Ah, Al, Bh, Bl
#define SMEM_BYTES (NSTG * STAGEB)    // 122880

typedef unsigned long long u64;

// ---------------- scratch ----------------
__device__ int   g_eid[2][NTOK];
__device__ float g_wt [2][NTOK];
__device__ int   g_cnt[2][NEXP];
__device__ int   g_cur[2][NEXP];
__device__ int   g_off[2][NEXP + 1];
__device__ int   g_ts [2][NEXP + 1];
__device__ int   g_bucket[2][NTOK];
__device__ float g_bw[2][NTOK];

__device__ __half g_xh[NTOK * HDIM];
__device__ __half g_xl[NTOK * HDIM];
__device__ __half g_wh[NEXP * HDIM * HDIM];
__device__ __half g_wl[NEXP * HDIM * HDIM];

// ---------------- helpers ----------------
__device__ __forceinline__ void cpa16(uint32_t s, const void* g) {
    asm volatile("cp.async.cg.shared.global [%0], [%1], 16;" :: "r"(s), "l"(g));
}
__device__ __forceinline__ void cp_commit() { asm volatile("cp.async.commit_group;"); }
template <int N> __device__ __forceinline__ void cp_wait() {
    asm volatile("cp.async.wait_group %0;" :: "n"(N));
}
__device__ __forceinline__ void mma16816(float* c, const uint32_t* a, const uint32_t* b) {
    asm volatile(
        "mma.sync.aligned.m16n8k16.row.col.f32.f16.f16.f32 "
        "{%0,%1,%2,%3}, {%4,%5,%6,%7}, {%8,%9}, {%0,%1,%2,%3};"
        : "+f"(c[0]), "+f"(c[1]), "+f"(c[2]), "+f"(c[3])
        : "r"(a[0]), "r"(a[1]), "r"(a[2]), "r"(a[3]), "r"(b[0]), "r"(b[1]));
}
__device__ __forceinline__ void ldsm4(uint32_t* r, uint32_t addr) {
    asm volatile("ldmatrix.sync.aligned.m8n8.x4.shared.b16 {%0,%1,%2,%3}, [%4];"
        : "=r"(r[0]), "=r"(r[1]), "=r"(r[2]), "=r"(r[3]) : "r"(addr));
}

// ---------------- kernel 0: zero counters ----------------
__global__ void init_kernel() {
    int t = threadIdx.x;
    if (t < 2 * NEXP) { ((int*)g_cnt)[t] = 0; ((int*)g_cur)[t] = 0; }
}

// ---------------- convert weights (fp32 -> fp16 hi/lo) ----------------
__global__ __launch_bounds__(256) void convw_kernel(const float* __restrict__ w) {
    int i = blockIdx.x * 256 + threadIdx.x;
    float v = w[i];
    __half h = __float2half(v);
    g_wh[i] = h;
    g_wl[i] = __float2half(v - __half2float(h));
}

// ---------------- kernel 1: router (fused x hi/lo conversion) ----------------
__global__ __launch_bounds__(256) void router_kernel(
    const float* __restrict__ x, const float* __restrict__ rw, const float* __restrict__ rb)
{
    __shared__ float s_rw[NEXP * HDIM];
    for (int i = threadIdx.x; i < NEXP * HDIM; i += 256) s_rw[i] = rw[i];
    __syncthreads();

    int warp = threadIdx.x >> 5, lane = threadIdx.x & 31;
    int tok = (blockIdx.x << 3) + warp;
    const float* xr = x + (size_t)tok * HDIM;
    __half* xh = g_xh + (size_t)tok * HDIM;
    __half* xl = g_xl + (size_t)tok * HDIM;

    float acc[NEXP];
#pragma unroll
    for (int e = 0; e < NEXP; e++) acc[e] = 0.f;
#pragma unroll 4
    for (int i = 0; i < HDIM / 32; i++) {
        float xv = xr[i * 32 + lane];
        __half h = __float2half(xv);
        xh[i * 32 + lane] = h;
        xl[i * 32 + lane] = __float2half(xv - __half2float(h));
#pragma unroll
        for (int e = 0; e < NEXP; e++)
            acc[e] = fmaf(xv, s_rw[e * HDIM + i * 32 + lane], acc[e]);
    }
#pragma unroll
    for (int e = 0; e < NEXP; e++)
#pragma unroll
        for (int o = 16; o > 0; o >>= 1)
            acc[e] += __shfl_xor_sync(0xffffffffu, acc[e], o);

    if (lane == 0) {
        float s[NEXP];
#pragma unroll
        for (int e = 0; e < NEXP; e++) s[e] = acc[e] + rb[e];
        float m = s[0];
#pragma unroll
        for (int e = 1; e < NEXP; e++) m = fmaxf(m, s[e]);
        float p[NEXP]; float Z = 0.f;
#pragma unroll
        for (int e = 0; e < NEXP; e++) { p[e] = expf(s[e] - m); Z += p[e]; }
        int e0 = 0;
#pragma unroll
        for (int e = 1; e < NEXP; e++) if (p[e] > p[e0]) e0 = e;
        int e1 = (e0 == 0) ? 1 : 0;
#pragma unroll
        for (int e = 0; e < NEXP; e++) if (e != e0 && p[e] > p[e1]) e1 = e;
        float p0 = p[e0] / Z, p1 = p[e1] / Z;
        float inv = 1.f / (p0 + p1 + 1e-9f);
        g_eid[0][tok] = e0; g_wt[0][tok] = p0 * inv;
        g_eid[1][tok] = e1; g_wt[1][tok] = p1 * inv;
        atomicAdd(&g_cnt[0][e0], 1);
        atomicAdd(&g_cnt[1][e1], 1);
    }
}

// ---------------- kernel 2: scan ----------------
__global__ void scan_kernel() {
    if (threadIdx.x == 0 && blockIdx.x == 0) {
        for (int s = 0; s < 2; s++) {
            int o = 0, t = 0;
            for (int e = 0; e < NEXP; e++) {
                g_off[s][e] = o; g_ts[s][e] = t;
                o += g_cnt[s][e];
                t += (g_cnt[s][e] + TM - 1) >> 7;
            }
            g_off[s][NEXP] = o; g_ts[s][NEXP] = t;
        }
    }
}

// ---------------- kernel 3: scatter ----------------
__global__ __launch_bounds__(256) void scatter_kernel() {
    int t = blockIdx.x * 256 + threadIdx.x;
    if (t >= NTOK) return;
#pragma unroll
    for (int s = 0; s < 2; s++) {
        int e = g_eid[s][t];
        int pos = g_off[s][e] + atomicAdd(&g_cur[s][e], 1);
        g_bucket[s][pos] = t;
        g_bw[s][pos] = g_wt[s][t];
    }
}

// ---------------- kernel 4: grouped GEMM via mma.sync + ldmatrix ----------------
template <int SLOT, bool ACC>
__global__ __launch_bounds__(256, 1)
void moe_mma(const float* __restrict__ eb, float* __restrict__ out)
{
    extern __shared__ __align__(128) char smem[];
    const uint32_t sb = (uint32_t)__cvta_generic_to_shared(smem);

    __shared__ int   sMeta[3];
    __shared__ int   sTok[CTM];
    __shared__ float sWgt[CTM];
    __shared__ float sBias[CTN];

    int tid = threadIdx.x;
    int wid = tid >> 5, lane = tid & 31;

    if (tid == 0) {
        int bx = blockIdx.x;
        if (bx >= g_ts[SLOT][NEXP]) sMeta[0] = -1;
        else {
            int e = 0;
            while (g_ts[SLOT][e + 1] <= bx) e++;
            sMeta[0] = e;
            sMeta[1] = g_off[SLOT][e] + ((bx - g_ts[SLOT][e]) << 7);
            sMeta[2] = g_off[SLOT][e + 1];
        }
    }
    __syncthreads();
    int e = sMeta[0];
    if (e < 0) return;
    int m0 = sMeta[1], mEnd = sMeta[2];
    int nBase = blockIdx.y << 7;   // * 128

    if (tid < CTM) {
        int p = m0 + tid;
        int pc = p < mEnd ? p : mEnd - 1;
        sTok[tid] = g_bucket[SLOT][pc];
        sWgt[tid] = g_bw[SLOT][pc];
        sBias[tid] = eb[e * HDIM + nBase + tid];
    }
    __syncthreads();

    // ---- stage loader: 8 cp.async(16B) per thread ----
    int lrow = tid >> 1;                 // 0..127
    int lc0  = (tid & 1) * 2;            // chunk 0 or 2
    size_t gAr = (size_t)sTok[lrow] * HDIM;
    size_t gBr = ((size_t)e * HDIM + nBase + lrow) * HDIM;

    auto load_stage = [&](int kt, int buf) {
        uint32_t sbase = sb + (uint32_t)buf * STAGEB;
        int kc = kt * CTK;
#pragma unroll
        for (int t = 0; t < 2; t++) {
            int c = lc0 + t;
            uint32_t so = (uint32_t)(lrow * ROWB + c * 16);
            size_t gA = gAr + kc + c * 8;
            size_t gB = gBr + kc + c * 8;
            cpa16(sbase + 0 * TILEB + so, g_xh + gA);
            cpa16(sbase + 1 * TILEB + so, g_xl + gA);
            cpa16(sbase + 2 * TILEB + so, g_wh + gB);
            cpa16(sbase + 3 * TILEB + so, g_wl + gB);
        }
    };

    load_stage(0, 0); cp_commit();
    load_stage(1, 1); cp_commit();

    int warp_m = wid >> 1, warp_n = wid & 1;
    int r = lane >> 2, q = lane & 3;

    // ldmatrix lane address offsets (bytes within a tile)
    // A: lanes 0-7 rows0-7/k0, 8-15 rows8-15/k0, 16-23 rows0-7/k+8, 24-31 rows8-15/k+8
    uint32_t aOff = (uint32_t)((warp_m * 32 + (lane & 15)) * ROWB + ((lane >> 4) << 4));
    // B: lanes 0-7 n0-7/k0, 8-15 n0-7/k+8, 16-23 n8-15/k0, 24-31 n8-15/k+8
    uint32_t bOff = (uint32_t)((warp_n * 64 + ((lane >> 4) << 3) + (lane & 7)) * ROWB
                               + (((lane >> 3) & 1) << 4));

    float acc[2][8][4];
#pragma unroll
    for (int mt = 0; mt < 2; mt++)
#pragma unroll
        for (int nt = 0; nt < 8; nt++)
#pragma unroll
            for (int i = 0; i < 4; i++) acc[mt][nt][i] = 0.f;

    for (int kt = 0; kt < KT; kt++) {
        int buf = kt % NSTG;
        if (kt == KT - 1) cp_wait<0>(); else cp_wait<1>();
        __syncthreads();
        if (kt + 2 < KT) { load_stage(kt + 2, (kt + 2) % NSTG); cp_commit(); }

        uint32_t tb = sb + (uint32_t)buf * STAGEB;

#pragma unroll
        for (int k16 = 0; k16 < 2; k16++) {
            uint32_t kb = (uint32_t)(k16 * 32);
            uint32_t ah[2][4], al[2][4], bh[8][2], bl[8][2];
#pragma unroll
            for (int mt = 0; mt < 2; mt++) {
                uint32_t a = tb + aOff + (uint32_t)(mt * 16 * ROWB) + kb;
                ldsm4(ah[mt], a);
                ldsm4(al[mt], a + TILEB);
            }
#pragma unroll
            for (int ntp = 0; ntp < 4; ntp++) {
                uint32_t regs[4];
                uint32_t a = tb + 2 * TILEB + bOff + (uint32_t)(ntp * 16 * ROWB) + kb;
                ldsm4(regs, a);
                bh[2 * ntp][0] = regs[0]; bh[2 * ntp][1] = regs[1];
                bh[2 * ntp + 1][0] = regs[2]; bh[2 * ntp + 1][1] = regs[3];
                ldsm4(regs, a + TILEB);
                bl[2 * ntp][0] = regs[0]; bl[2 * ntp][1] = regs[1];
                bl[2 * ntp + 1][0] = regs[2]; bl[2 * ntp + 1][1] = regs[3];
            }
#pragma unroll
            for (int mt = 0; mt < 2; mt++)
#pragma unroll
                for (int nt = 0; nt < 8; nt++) {
                    mma16816(acc[mt][nt], ah[mt], bh[nt]);
                    mma16816(acc[mt][nt], ah[mt], bl[nt]);
                    mma16816(acc[mt][nt], al[mt], bh[nt]);
                }
        }
    }

    // ---- epilogue ----
#pragma unroll
    for (int mt = 0; mt < 2; mt++) {
        int lr0 = warp_m * 32 + mt * 16 + r;
        int lr1 = lr0 + 8;
        bool v0 = (m0 + lr0) < mEnd;
        bool v1 = (m0 + lr1) < mEnd;
        float w0 = sWgt[lr0], w1 = sWgt[lr1];
        float* o0 = out + (size_t)sTok[lr0] * HDIM + nBase;
        float* o1 = out + (size_t)sTok[lr1] * HDIM + nBase;
#pragma unroll
        for (int nt = 0; nt < 8; nt++) {
            int lc = warp_n * 64 + nt * 8 + 2 * q;
            float bx = sBias[lc], by = sBias[lc + 1];
            if (v0) {
                float2 v;
                v.x = w0 * (acc[mt][nt][0] + bx);
                v.y = w0 * (acc[mt][nt][1] + by);
                float2* dst = (float2*)(o0 + lc);
                if (ACC) { float2 o = *dst; o.x += v.x; o.y += v.y; *dst = o; }
                else *dst = v;
            }
            if (v1) {
                float2 v;
                v.x = w1 * (acc[mt][nt][2] + bx);
                v.y = w1 * (acc[mt][nt][3] + by);
                float2* dst = (float2*)(o1 + lc);
                if (ACC) { float2 o = *dst; o.x += v.x; o.y += v.y; *dst = o; }
                else *dst = v;
            }
        }
    }
}

// ---------------- launch ----------------
extern "C" void kernel_launch(void* const* d_in, const int* in_sizes, int n_in,
                              void* d_out, int out_size)
{
    const float* x  = (const float*)d_in[0];
    const float* rw = (const float*)d_in[1];
    const float* rb = (const float*)d_in[2];
    const float* ew = (const float*)d_in[3];
    const float* eb = (const float*)d_in[4];
    float* out = (float*)d_out;
    (void)in_sizes; (void)n_in; (void)out_size;

    cudaFuncSetAttribute(moe_mma<0, false>, cudaFuncAttributeMaxDynamicSharedMemorySize, SMEM_BYTES);
    cudaFuncSetAttribute(moe_mma<1, true >, cudaFuncAttributeMaxDynamicSharedMemorySize, SMEM_BYTES);

    init_kernel<<<1, 32>>>();
    convw_kernel<<<NEXP * HDIM * HDIM / 256, 256>>>(ew);
    router_kernel<<<NTOK / 8, 256>>>(x, rw, rb);
    scan_kernel<<<1, 32>>>();
    scatter_kernel<<<NTOK / 256, 256>>>();
    moe_mma<0, false><<<dim3(MAXTILES, HDIM / CTN), 256, SMEM_BYTES>>>(eb, out);
    moe_mma<1, true ><<<dim3(MAXTILES, HDIM / CTN), 256, SMEM_BYTES>>>(eb, out);
}

// round 5
// speedup vs baseline: 2.8962x; 1.2406x over previous
#include <cuda_runtime.h>
#include <cuda_fp16.h>
#include <cstdint>

#define NTOK 32768
#define HDIM 768
#define NEXP 8
#define TM 128
#define MAXTILES (NTOK / TM + NEXP)  // 264

// GEMM tiles
#define CTM 128
#define CTN 128
#define CTK 32                        // halves per k-stage
#define KT  (HDIM / CTK)              // 24 stages
#define NSTG 4
#define ROWB 80                       // padded row stride bytes (32 halves + 8 pad)
#define TILEB (128 * ROWB)            // 10240 bytes per (128 x 32) half tile
#define STAGEB (3 * TILEB)            // Ah, Bh, Bl
#define SMEM_BYTES (NSTG * STAGEB)    // 122880

typedef unsigned long long u64;

// ---------------- scratch ----------------
__device__ int   g_eid[2][NTOK];
__device__ float g_wt [2][NTOK];
__device__ int   g_cnt[2][NEXP];
__device__ int   g_cur[2][NEXP];
__device__ int   g_off[2][NEXP + 1];
__device__ int   g_ts [2][NEXP + 1];
__device__ int   g_bucket[2][NTOK];
__device__ float g_bw[2][NTOK];

__device__ __half g_xh[NTOK * HDIM];
__device__ __half g_wh[NEXP * HDIM * HDIM];
__device__ __half g_wl[NEXP * HDIM * HDIM];

// ---------------- helpers ----------------
__device__ __forceinline__ void cpa16(uint32_t s, const void* g) {
    asm volatile("cp.async.cg.shared.global [%0], [%1], 16;" :: "r"(s), "l"(g));
}
__device__ __forceinline__ void cp_commit() { asm volatile("cp.async.commit_group;"); }
template <int N> __device__ __forceinline__ void cp_wait() {
    asm volatile("cp.async.wait_group %0;" :: "n"(N));
}
__device__ __forceinline__ void mma16816_f32(float* c, const uint32_t* a, const uint32_t* b) {
    asm volatile(
        "mma.sync.aligned.m16n8k16.row.col.f32.f16.f16.f32 "
        "{%0,%1,%2,%3}, {%4,%5,%6,%7}, {%8,%9}, {%0,%1,%2,%3};"
        : "+f"(c[0]), "+f"(c[1]), "+f"(c[2]), "+f"(c[3])
        : "r"(a[0]), "r"(a[1]), "r"(a[2]), "r"(a[3]), "r"(b[0]), "r"(b[1]));
}
__device__ __forceinline__ void mma16816_f16(uint32_t* c, const uint32_t* a, const uint32_t* b) {
    asm volatile(
        "mma.sync.aligned.m16n8k16.row.col.f16.f16.f16.f16 "
        "{%0,%1}, {%2,%3,%4,%5}, {%6,%7}, {%0,%1};"
        : "+r"(c[0]), "+r"(c[1])
        : "r"(a[0]), "r"(a[1]), "r"(a[2]), "r"(a[3]), "r"(b[0]), "r"(b[1]));
}
__device__ __forceinline__ void ldsm4(uint32_t* r, uint32_t addr) {
    asm volatile("ldmatrix.sync.aligned.m8n8.x4.shared.b16 {%0,%1,%2,%3}, [%4];"
        : "=r"(r[0]), "=r"(r[1]), "=r"(r[2]), "=r"(r[3]) : "r"(addr));
}

// ---------------- kernel 0: zero counters ----------------
__global__ void init_kernel() {
    int t = threadIdx.x;
    if (t < 2 * NEXP) { ((int*)g_cnt)[t] = 0; ((int*)g_cur)[t] = 0; }
}

// ---------------- convert weights (fp32 -> fp16 hi/lo) ----------------
__global__ __launch_bounds__(256) void convw_kernel(const float* __restrict__ w) {
    int i = blockIdx.x * 256 + threadIdx.x;
    float v = w[i];
    __half h = __float2half(v);
    g_wh[i] = h;
    g_wl[i] = __float2half(v - __half2float(h));
}

// ---------------- kernel 1: router (fused x hi conversion) ----------------
__global__ __launch_bounds__(256) void router_kernel(
    const float* __restrict__ x, const float* __restrict__ rw, const float* __restrict__ rb)
{
    __shared__ float s_rw[NEXP * HDIM];
    for (int i = threadIdx.x; i < NEXP * HDIM; i += 256) s_rw[i] = rw[i];
    __syncthreads();

    int warp = threadIdx.x >> 5, lane = threadIdx.x & 31;
    int tok = (blockIdx.x << 3) + warp;
    const float* xr = x + (size_t)tok * HDIM;
    __half* xh = g_xh + (size_t)tok * HDIM;

    float acc[NEXP];
#pragma unroll
    for (int e = 0; e < NEXP; e++) acc[e] = 0.f;
#pragma unroll 4
    for (int i = 0; i < HDIM / 32; i++) {
        float xv = xr[i * 32 + lane];
        xh[i * 32 + lane] = __float2half(xv);
#pragma unroll
        for (int e = 0; e < NEXP; e++)
            acc[e] = fmaf(xv, s_rw[e * HDIM + i * 32 + lane], acc[e]);
    }
#pragma unroll
    for (int e = 0; e < NEXP; e++)
#pragma unroll
        for (int o = 16; o > 0; o >>= 1)
            acc[e] += __shfl_xor_sync(0xffffffffu, acc[e], o);

    if (lane == 0) {
        float s[NEXP];
#pragma unroll
        for (int e = 0; e < NEXP; e++) s[e] = acc[e] + rb[e];
        float m = s[0];
#pragma unroll
        for (int e = 1; e < NEXP; e++) m = fmaxf(m, s[e]);
        float p[NEXP]; float Z = 0.f;
#pragma unroll
        for (int e = 0; e < NEXP; e++) { p[e] = expf(s[e] - m); Z += p[e]; }
        int e0 = 0;
#pragma unroll
        for (int e = 1; e < NEXP; e++) if (p[e] > p[e0]) e0 = e;
        int e1 = (e0 == 0) ? 1 : 0;
#pragma unroll
        for (int e = 0; e < NEXP; e++) if (e != e0 && p[e] > p[e1]) e1 = e;
        float p0 = p[e0] / Z, p1 = p[e1] / Z;
        float inv = 1.f / (p0 + p1 + 1e-9f);
        g_eid[0][tok] = e0; g_wt[0][tok] = p0 * inv;
        g_eid[1][tok] = e1; g_wt[1][tok] = p1 * inv;
        atomicAdd(&g_cnt[0][e0], 1);
        atomicAdd(&g_cnt[1][e1], 1);
    }
}

// ---------------- kernel 2: scan ----------------
__global__ void scan_kernel() {
    if (threadIdx.x == 0 && blockIdx.x == 0) {
        for (int s = 0; s < 2; s++) {
            int o = 0, t = 0;
            for (int e = 0; e < NEXP; e++) {
                g_off[s][e] = o; g_ts[s][e] = t;
                o += g_cnt[s][e];
                t += (g_cnt[s][e] + TM - 1) >> 7;
            }
            g_off[s][NEXP] = o; g_ts[s][NEXP] = t;
        }
    }
}

// ---------------- kernel 3: scatter ----------------
__global__ __launch_bounds__(256) void scatter_kernel() {
    int t = blockIdx.x * 256 + threadIdx.x;
    if (t >= NTOK) return;
#pragma unroll
    for (int s = 0; s < 2; s++) {
        int e = g_eid[s][t];
        int pos = g_off[s][e] + atomicAdd(&g_cur[s][e], 1);
        g_bucket[s][pos] = t;
        g_bw[s][pos] = g_wt[s][t];
    }
}

// ---------------- kernel 4: grouped GEMM: Ah*(Bh f32-acc + Bl f16-acc) ----------------
template <int SLOT, bool ACC>
__global__ __launch_bounds__(256, 1)
void moe_mma(const float* __restrict__ eb, float* __restrict__ out)
{
    extern __shared__ __align__(128) char smem[];
    const uint32_t sb = (uint32_t)__cvta_generic_to_shared(smem);

    __shared__ int   sMeta[3];
    __shared__ int   sTok[CTM];
    __shared__ float sWgt[CTM];
    __shared__ float sBias[CTN];

    int tid = threadIdx.x;
    int wid = tid >> 5, lane = tid & 31;

    if (tid == 0) {
        int bx = blockIdx.x;
        if (bx >= g_ts[SLOT][NEXP]) sMeta[0] = -1;
        else {
            int e = 0;
            while (g_ts[SLOT][e + 1] <= bx) e++;
            sMeta[0] = e;
            sMeta[1] = g_off[SLOT][e] + ((bx - g_ts[SLOT][e]) << 7);
            sMeta[2] = g_off[SLOT][e + 1];
        }
    }
    __syncthreads();
    int e = sMeta[0];
    if (e < 0) return;
    int m0 = sMeta[1], mEnd = sMeta[2];
    int nBase = blockIdx.y << 7;   // * 128

    if (tid < CTM) {
        int p = m0 + tid;
        int pc = p < mEnd ? p : mEnd - 1;
        sTok[tid] = g_bucket[SLOT][pc];
        sWgt[tid] = g_bw[SLOT][pc];
        sBias[tid] = eb[e * HDIM + nBase + tid];
    }
    __syncthreads();

    // ---- stage loader: 6 cp.async(16B) per thread (Ah, Bh, Bl) ----
    int lrow = tid >> 1;                 // 0..127
    int lc0  = (tid & 1) * 2;            // chunk 0 or 2
    size_t gAr = (size_t)sTok[lrow] * HDIM;
    size_t gBr = ((size_t)e * HDIM + nBase + lrow) * HDIM;

    auto load_stage = [&](int kt, int buf) {
        uint32_t sbase = sb + (uint32_t)buf * STAGEB;
        int kc = kt * CTK;
#pragma unroll
        for (int t = 0; t < 2; t++) {
            int c = lc0 + t;
            uint32_t so = (uint32_t)(lrow * ROWB + c * 16);
            size_t gA = gAr + kc + c * 8;
            size_t gB = gBr + kc + c * 8;
            cpa16(sbase + 0 * TILEB + so, g_xh + gA);
            cpa16(sbase + 1 * TILEB + so, g_wh + gB);
            cpa16(sbase + 2 * TILEB + so, g_wl + gB);
        }
    };

    load_stage(0, 0); cp_commit();
    load_stage(1, 1); cp_commit();
    load_stage(2, 2); cp_commit();

    int warp_m = wid >> 1, warp_n = wid & 1;
    int r = lane >> 2, q = lane & 3;

    // ldmatrix lane address offsets (bytes within a tile)
    uint32_t aOff = (uint32_t)((warp_m * 32 + (lane & 15)) * ROWB + ((lane >> 4) << 4));
    uint32_t bOff = (uint32_t)((warp_n * 64 + ((lane >> 4) << 3) + (lane & 7)) * ROWB
                               + (((lane >> 3) & 1) << 4));

    float acc[2][8][4];
    uint32_t accl[2][8][2];
#pragma unroll
    for (int mt = 0; mt < 2; mt++)
#pragma unroll
        for (int nt = 0; nt < 8; nt++) {
#pragma unroll
            for (int i = 0; i < 4; i++) acc[mt][nt][i] = 0.f;
            accl[mt][nt][0] = 0u; accl[mt][nt][1] = 0u;
        }

    for (int kt = 0; kt < KT; kt++) {
        int buf = kt & 3;   // NSTG = 4
        if (kt <= KT - 3) cp_wait<2>();
        else if (kt == KT - 2) cp_wait<1>();
        else cp_wait<0>();
        __syncthreads();
        if (kt + 3 < KT) { load_stage(kt + 3, (kt + 3) & 3); cp_commit(); }

        uint32_t tb = sb + (uint32_t)buf * STAGEB;

#pragma unroll
        for (int k16 = 0; k16 < 2; k16++) {
            uint32_t kb = (uint32_t)(k16 * 32);
            uint32_t ah[2][4], bh[8][2], bl[8][2];
#pragma unroll
            for (int mt = 0; mt < 2; mt++)
                ldsm4(ah[mt], tb + aOff + (uint32_t)(mt * 16 * ROWB) + kb);
#pragma unroll
            for (int ntp = 0; ntp < 4; ntp++) {
                uint32_t regs[4];
                uint32_t a = tb + TILEB + bOff + (uint32_t)(ntp * 16 * ROWB) + kb;
                ldsm4(regs, a);
                bh[2 * ntp][0] = regs[0]; bh[2 * ntp][1] = regs[1];
                bh[2 * ntp + 1][0] = regs[2]; bh[2 * ntp + 1][1] = regs[3];
                ldsm4(regs, a + TILEB);
                bl[2 * ntp][0] = regs[0]; bl[2 * ntp][1] = regs[1];
                bl[2 * ntp + 1][0] = regs[2]; bl[2 * ntp + 1][1] = regs[3];
            }
#pragma unroll
            for (int mt = 0; mt < 2; mt++)
#pragma unroll
                for (int nt = 0; nt < 8; nt++) {
                    mma16816_f32(acc[mt][nt], ah[mt], bh[nt]);
                    mma16816_f16(accl[mt][nt], ah[mt], bl[nt]);
                }
        }
    }

    // ---- epilogue: merge f32 main + f16 correction, scale, scatter ----
#pragma unroll
    for (int mt = 0; mt < 2; mt++) {
        int lr0 = warp_m * 32 + mt * 16 + r;
        int lr1 = lr0 + 8;
        bool v0 = (m0 + lr0) < mEnd;
        bool v1 = (m0 + lr1) < mEnd;
        float w0 = sWgt[lr0], w1 = sWgt[lr1];
        float* o0 = out + (size_t)sTok[lr0] * HDIM + nBase;
        float* o1 = out + (size_t)sTok[lr1] * HDIM + nBase;
#pragma unroll
        for (int nt = 0; nt < 8; nt++) {
            int lc = warp_n * 64 + nt * 8 + 2 * q;
            float bx = sBias[lc], by = sBias[lc + 1];
            __half2 h0 = *(__half2*)&accl[mt][nt][0];
            __half2 h1 = *(__half2*)&accl[mt][nt][1];
            float2 c0 = __half22float2(h0);
            float2 c1 = __half22float2(h1);
            if (v0) {
                float2 v;
                v.x = w0 * (acc[mt][nt][0] + c0.x + bx);
                v.y = w0 * (acc[mt][nt][1] + c0.y + by);
                float2* dst = (float2*)(o0 + lc);
                if (ACC) { float2 o = *dst; o.x += v.x; o.y += v.y; *dst = o; }
                else *dst = v;
            }
            if (v1) {
                float2 v;
                v.x = w1 * (acc[mt][nt][2] + c1.x + bx);
                v.y = w1 * (acc[mt][nt][3] + c1.y + by);
                float2* dst = (float2*)(o1 + lc);
                if (ACC) { float2 o = *dst; o.x += v.x; o.y += v.y; *dst = o; }
                else *dst = v;
            }
        }
    }
}

// ---------------- launch ----------------
extern "C" void kernel_launch(void* const* d_in, const int* in_sizes, int n_in,
                              void* d_out, int out_size)
{
    const float* x  = (const float*)d_in[0];
    const float* rw = (const float*)d_in[1];
    const float* rb = (const float*)d_in[2];
    const float* ew = (const float*)d_in[3];
    const float* eb = (const float*)d_in[4];
    float* out = (float*)d_out;
    (void)in_sizes; (void)n_in; (void)out_size;

    cudaFuncSetAttribute(moe_mma<0, false>, cudaFuncAttributeMaxDynamicSharedMemorySize, SMEM_BYTES);
    cudaFuncSetAttribute(moe_mma<1, true >, cudaFuncAttributeMaxDynamicSharedMemorySize, SMEM_BYTES);

    init_kernel<<<1, 32>>>();
    convw_kernel<<<NEXP * HDIM * HDIM / 256, 256>>>(ew);
    router_kernel<<<NTOK / 8, 256>>>(x, rw, rb);
    scan_kernel<<<1, 32>>>();
    scatter_kernel<<<NTOK / 256, 256>>>();
    moe_mma<0, false><<<dim3(MAXTILES, HDIM / CTN), 256, SMEM_BYTES>>>(eb, out);
    moe_mma<1, true ><<<dim3(MAXTILES, HDIM / CTN), 256, SMEM_BYTES>>>(eb, out);
}

// round 6
// speedup vs baseline: 4.0497x; 1.3983x over previous
#include <cuda_runtime.h>
#include <cuda_fp16.h>
#include <cstdint>

#define NTOK 32768
#define HDIM 768
#define NEXP 8
#define TM 128
#define MAXTILES (NTOK / TM + NEXP)  // 264

// GEMM tiles
#define CTM 128
#define CTN 128
#define CTK 32                        // halves per k-stage
#define KT  (HDIM / CTK)              // 24 stages
#define NSTG 4
#define ROWB 80                       // padded row stride bytes (32 halves + 8 pad)
#define TILEB (128 * ROWB)            // 10240 bytes per (128 x 32) half tile
#define STAGEB (2 * TILEB)            // Ah, Bh
#define SMEM_BYTES (NSTG * STAGEB)    // 81920

typedef unsigned long long u64;

// ---------------- scratch ----------------
__device__ int   g_eid[2][NTOK];
__device__ float g_wt [2][NTOK];
__device__ int   g_cnt[2][NEXP];
__device__ int   g_cur[2][NEXP];
__device__ int   g_off[2][NEXP + 1];
__device__ int   g_ts [2][NEXP + 1];
__device__ int   g_bucket[2][NTOK];
__device__ float g_bw[2][NTOK];

__device__ __half g_xh[NTOK * HDIM];
__device__ __half g_wh[NEXP * HDIM * HDIM];

// ---------------- helpers ----------------
__device__ __forceinline__ void cpa16(uint32_t s, const void* g) {
    asm volatile("cp.async.cg.shared.global [%0], [%1], 16;" :: "r"(s), "l"(g));
}
__device__ __forceinline__ void cp_commit() { asm volatile("cp.async.commit_group;"); }
template <int N> __device__ __forceinline__ void cp_wait() {
    asm volatile("cp.async.wait_group %0;" :: "n"(N));
}
__device__ __forceinline__ void mma16816_f32(float* c, const uint32_t* a, const uint32_t* b) {
    asm volatile(
        "mma.sync.aligned.m16n8k16.row.col.f32.f16.f16.f32 "
        "{%0,%1,%2,%3}, {%4,%5,%6,%7}, {%8,%9}, {%0,%1,%2,%3};"
        : "+f"(c[0]), "+f"(c[1]), "+f"(c[2]), "+f"(c[3])
        : "r"(a[0]), "r"(a[1]), "r"(a[2]), "r"(a[3]), "r"(b[0]), "r"(b[1]));
}
__device__ __forceinline__ void ldsm4(uint32_t* r, uint32_t addr) {
    asm volatile("ldmatrix.sync.aligned.m8n8.x4.shared.b16 {%0,%1,%2,%3}, [%4];"
        : "=r"(r[0]), "=r"(r[1]), "=r"(r[2]), "=r"(r[3]) : "r"(addr));
}

// ---------------- kernel 0: zero counters ----------------
__global__ void init_kernel() {
    int t = threadIdx.x;
    if (t < 2 * NEXP) { ((int*)g_cnt)[t] = 0; ((int*)g_cur)[t] = 0; }
}

// ---------------- convert weights (fp32 -> fp16 hi), vectorized ----------------
__global__ __launch_bounds__(256) void convw_kernel(const float* __restrict__ w) {
    int i = blockIdx.x * 256 + threadIdx.x;       // one float4 per thread
    float4 v = ((const float4*)w)[i];
    __half2 h0 = __floats2half2_rn(v.x, v.y);
    __half2 h1 = __floats2half2_rn(v.z, v.w);
    ((__half2*)g_wh)[2 * i] = h0;
    ((__half2*)g_wh)[2 * i + 1] = h1;
}

// ---------------- kernel 1: router (fused x hi conversion, float4 path) ----------------
__global__ __launch_bounds__(256) void router_kernel(
    const float* __restrict__ x, const float* __restrict__ rw, const float* __restrict__ rb)
{
    __shared__ float s_rw[NEXP * HDIM];
    for (int i = threadIdx.x; i < NEXP * HDIM; i += 256) s_rw[i] = rw[i];
    __syncthreads();

    int warp = threadIdx.x >> 5, lane = threadIdx.x & 31;
    int tok = (blockIdx.x << 3) + warp;
    const float4* xr = (const float4*)(x + (size_t)tok * HDIM);
    __half2* xh = (__half2*)(g_xh + (size_t)tok * HDIM);

    float acc[NEXP];
#pragma unroll
    for (int e = 0; e < NEXP; e++) acc[e] = 0.f;
#pragma unroll
    for (int i = 0; i < HDIM / 128; i++) {        // 6 iters of float4
        int idx = i * 32 + lane;
        float4 v = xr[idx];
        xh[2 * idx]     = __floats2half2_rn(v.x, v.y);
        xh[2 * idx + 1] = __floats2half2_rn(v.z, v.w);
#pragma unroll
        for (int e = 0; e < NEXP; e++) {
            float4 w4 = ((const float4*)(s_rw + e * HDIM))[idx];
            acc[e] = fmaf(v.x, w4.x, fmaf(v.y, w4.y, fmaf(v.z, w4.z, fmaf(v.w, w4.w, acc[e]))));
        }
    }
#pragma unroll
    for (int e = 0; e < NEXP; e++)
#pragma unroll
        for (int o = 16; o > 0; o >>= 1)
            acc[e] += __shfl_xor_sync(0xffffffffu, acc[e], o);

    if (lane == 0) {
        float s[NEXP];
#pragma unroll
        for (int e = 0; e < NEXP; e++) s[e] = acc[e] + rb[e];
        float m = s[0];
#pragma unroll
        for (int e = 1; e < NEXP; e++) m = fmaxf(m, s[e]);
        float p[NEXP]; float Z = 0.f;
#pragma unroll
        for (int e = 0; e < NEXP; e++) { p[e] = expf(s[e] - m); Z += p[e]; }
        int e0 = 0;
#pragma unroll
        for (int e = 1; e < NEXP; e++) if (p[e] > p[e0]) e0 = e;
        int e1 = (e0 == 0) ? 1 : 0;
#pragma unroll
        for (int e = 0; e < NEXP; e++) if (e != e0 && p[e] > p[e1]) e1 = e;
        float p0 = p[e0] / Z, p1 = p[e1] / Z;
        float inv = 1.f / (p0 + p1 + 1e-9f);
        g_eid[0][tok] = e0; g_wt[0][tok] = p0 * inv;
        g_eid[1][tok] = e1; g_wt[1][tok] = p1 * inv;
        atomicAdd(&g_cnt[0][e0], 1);
        atomicAdd(&g_cnt[1][e1], 1);
    }
}

// ---------------- kernel 2: scan ----------------
__global__ void scan_kernel() {
    if (threadIdx.x == 0 && blockIdx.x == 0) {
        for (int s = 0; s < 2; s++) {
            int o = 0, t = 0;
            for (int e = 0; e < NEXP; e++) {
                g_off[s][e] = o; g_ts[s][e] = t;
                o += g_cnt[s][e];
                t += (g_cnt[s][e] + TM - 1) >> 7;
            }
            g_off[s][NEXP] = o; g_ts[s][NEXP] = t;
        }
    }
}

// ---------------- kernel 3: scatter ----------------
__global__ __launch_bounds__(256) void scatter_kernel() {
    int t = blockIdx.x * 256 + threadIdx.x;
    if (t >= NTOK) return;
#pragma unroll
    for (int s = 0; s < 2; s++) {
        int e = g_eid[s][t];
        int pos = g_off[s][e] + atomicAdd(&g_cur[s][e], 1);
        g_bucket[s][pos] = t;
        g_bw[s][pos] = g_wt[s][t];
    }
}

// ---------------- kernel 4: grouped GEMM, fp16 x fp16 -> f32 accum ----------------
template <int SLOT, bool ACC>
__global__ __launch_bounds__(256, 1)
void moe_mma(const float* __restrict__ eb, float* __restrict__ out)
{
    extern __shared__ __align__(128) char smem[];
    const uint32_t sb = (uint32_t)__cvta_generic_to_shared(smem);

    __shared__ int   sMeta[3];
    __shared__ int   sTok[CTM];
    __shared__ float sWgt[CTM];
    __shared__ float sBias[CTN];

    int tid = threadIdx.x;
    int wid = tid >> 5, lane = tid & 31;

    if (tid == 0) {
        int bx = blockIdx.x;
        if (bx >= g_ts[SLOT][NEXP]) sMeta[0] = -1;
        else {
            int e = 0;
            while (g_ts[SLOT][e + 1] <= bx) e++;
            sMeta[0] = e;
            sMeta[1] = g_off[SLOT][e] + ((bx - g_ts[SLOT][e]) << 7);
            sMeta[2] = g_off[SLOT][e + 1];
        }
    }
    __syncthreads();
    int e = sMeta[0];
    if (e < 0) return;
    int m0 = sMeta[1], mEnd = sMeta[2];
    int nBase = blockIdx.y << 7;   // * 128

    if (tid < CTM) {
        int p = m0 + tid;
        int pc = p < mEnd ? p : mEnd - 1;
        sTok[tid] = g_bucket[SLOT][pc];
        sWgt[tid] = g_bw[SLOT][pc];
        sBias[tid] = eb[e * HDIM + nBase + tid];
    }
    __syncthreads();

    // ---- stage loader: 4 cp.async(16B) per thread (Ah, Bh) ----
    int lrow = tid >> 1;                 // 0..127
    int lc0  = (tid & 1) * 2;            // chunk 0 or 2
    size_t gAr = (size_t)sTok[lrow] * HDIM;
    size_t gBr = ((size_t)e * HDIM + nBase + lrow) * HDIM;

    auto load_stage = [&](int kt, int buf) {
        uint32_t sbase = sb + (uint32_t)buf * STAGEB;
        int kc = kt * CTK;
#pragma unroll
        for (int t = 0; t < 2; t++) {
            int c = lc0 + t;
            uint32_t so = (uint32_t)(lrow * ROWB + c * 16);
            cpa16(sbase + 0 * TILEB + so, g_xh + gAr + kc + c * 8);
            cpa16(sbase + 1 * TILEB + so, g_wh + gBr + kc + c * 8);
        }
    };

    load_stage(0, 0); cp_commit();
    load_stage(1, 1); cp_commit();
    load_stage(2, 2); cp_commit();

    int warp_m = wid >> 1, warp_n = wid & 1;
    int r = lane >> 2, q = lane & 3;

    // ldmatrix lane address offsets (bytes within a tile)
    uint32_t aOff = (uint32_t)((warp_m * 32 + (lane & 15)) * ROWB + ((lane >> 4) << 4));
    uint32_t bOff = (uint32_t)((warp_n * 64 + ((lane >> 4) << 3) + (lane & 7)) * ROWB
                               + (((lane >> 3) & 1) << 4));

    float acc[2][8][4];
#pragma unroll
    for (int mt = 0; mt < 2; mt++)
#pragma unroll
        for (int nt = 0; nt < 8; nt++)
#pragma unroll
            for (int i = 0; i < 4; i++) acc[mt][nt][i] = 0.f;

    for (int kt = 0; kt < KT; kt++) {
        int buf = kt & 3;   // NSTG = 4
        if (kt <= KT - 3) cp_wait<2>();
        else if (kt == KT - 2) cp_wait<1>();
        else cp_wait<0>();
        __syncthreads();
        if (kt + 3 < KT) { load_stage(kt + 3, (kt + 3) & 3); cp_commit(); }

        uint32_t tb = sb + (uint32_t)buf * STAGEB;

#pragma unroll
        for (int k16 = 0; k16 < 2; k16++) {
            uint32_t kb = (uint32_t)(k16 * 32);
            uint32_t ah[2][4], bh[8][2];
#pragma unroll
            for (int mt = 0; mt < 2; mt++)
                ldsm4(ah[mt], tb + aOff + (uint32_t)(mt * 16 * ROWB) + kb);
#pragma unroll
            for (int ntp = 0; ntp < 4; ntp++) {
                uint32_t regs[4];
                ldsm4(regs, tb + TILEB + bOff + (uint32_t)(ntp * 16 * ROWB) + kb);
                bh[2 * ntp][0] = regs[0]; bh[2 * ntp][1] = regs[1];
                bh[2 * ntp + 1][0] = regs[2]; bh[2 * ntp + 1][1] = regs[3];
            }
#pragma unroll
            for (int mt = 0; mt < 2; mt++)
#pragma unroll
                for (int nt = 0; nt < 8; nt++)
                    mma16816_f32(acc[mt][nt], ah[mt], bh[nt]);
        }
    }

    // ---- epilogue ----
#pragma unroll
    for (int mt = 0; mt < 2; mt++) {
        int lr0 = warp_m * 32 + mt * 16 + r;
        int lr1 = lr0 + 8;
        bool v0 = (m0 + lr0) < mEnd;
        bool v1 = (m0 + lr1) < mEnd;
        float w0 = sWgt[lr0], w1 = sWgt[lr1];
        float* o0 = out + (size_t)sTok[lr0] * HDIM + nBase;
        float* o1 = out + (size_t)sTok[lr1] * HDIM + nBase;
#pragma unroll
        for (int nt = 0; nt < 8; nt++) {
            int lc = warp_n * 64 + nt * 8 + 2 * q;
            float bx = sBias[lc], by = sBias[lc + 1];
            if (v0) {
                float2 v;
                v.x = w0 * (acc[mt][nt][0] + bx);
                v.y = w0 * (acc[mt][nt][1] + by);
                float2* dst = (float2*)(o0 + lc);
                if (ACC) { float2 o = *dst; o.x += v.x; o.y += v.y; *dst = o; }
                else *dst = v;
            }
            if (v1) {
                float2 v;
                v.x = w1 * (acc[mt][nt][2] + bx);
                v.y = w1 * (acc[mt][nt][3] + by);
                float2* dst = (float2*)(o1 + lc);
                if (ACC) { float2 o = *dst; o.x += v.x; o.y += v.y; *dst = o; }
                else *dst = v;
            }
        }
    }
}

// ---------------- launch ----------------
extern "C" void kernel_launch(void* const* d_in, const int* in_sizes, int n_in,
                              void* d_out, int out_size)
{
    const float* x  = (const float*)d_in[0];
    const float* rw = (const float*)d_in[1];
    const float* rb = (const float*)d_in[2];
    const float* ew = (const float*)d_in[3];
    const float* eb = (const float*)d_in[4];
    float* out = (float*)d_out;
    (void)in_sizes; (void)n_in; (void)out_size;

    cudaFuncSetAttribute(moe_mma<0, false>, cudaFuncAttributeMaxDynamicSharedMemorySize, SMEM_BYTES);
    cudaFuncSetAttribute(moe_mma<1, true >, cudaFuncAttributeMaxDynamicSharedMemorySize, SMEM_BYTES);

    init_kernel<<<1, 32>>>();
    convw_kernel<<<NEXP * HDIM * HDIM / 1024, 256>>>(ew);
    router_kernel<<<NTOK / 8, 256>>>(x, rw, rb);
    scan_kernel<<<1, 32>>>();
    scatter_kernel<<<NTOK / 256, 256>>>();
    moe_mma<0, false><<<dim3(MAXTILES, HDIM / CTN), 256, SMEM_BYTES>>>(eb, out);
    moe_mma<1, true ><<<dim3(MAXTILES, HDIM / CTN), 256, SMEM_BYTES>>>(eb, out);
}

// round 7
// speedup vs baseline: 5.6162x; 1.3868x over previous
#include <cuda_runtime.h>
#include <cuda_fp16.h>
#include <cstdint>

#define NTOK 32768
#define HDIM 768
#define NEXP 8
#define TM 128
#define MAXTILES (NTOK / TM + NEXP)  // 264

// GEMM tiles
#define CTM 128
#define CTN 128
#define CTK 32                        // halves per k-stage
#define KT  (HDIM / CTK)              // 24 stages
#define NSTG 4
#define ROWB 80                       // padded row stride bytes (32 halves + 8 pad)
#define TILEB (128 * ROWB)            // 10240 bytes per (128 x 32) half tile
#define STAGEB (2 * TILEB)            // Ah, Bh
#define SMEM_BYTES (NSTG * STAGEB)    // 81920 -> 2 CTAs/SM fit in 227KB

typedef unsigned long long u64;

// ---------------- scratch ----------------
__device__ int   g_eid[2][NTOK];
__device__ float g_wt [2][NTOK];
__device__ int   g_cnt[2][NEXP];
__device__ int   g_cur[2][NEXP];
__device__ int   g_off[2][NEXP + 1];
__device__ int   g_ts [2][NEXP + 1];
__device__ int   g_bucket[2][NTOK];
__device__ float g_bw[2][NTOK];

__device__ __half g_xh[NTOK * HDIM];
__device__ __half g_wh[NEXP * HDIM * HDIM];

// ---------------- helpers ----------------
__device__ __forceinline__ void cpa16(uint32_t s, const void* g) {
    asm volatile("cp.async.cg.shared.global [%0], [%1], 16;" :: "r"(s), "l"(g));
}
__device__ __forceinline__ void cp_commit() { asm volatile("cp.async.commit_group;"); }
template <int N> __device__ __forceinline__ void cp_wait() {
    asm volatile("cp.async.wait_group %0;" :: "n"(N));
}
__device__ __forceinline__ void mma16816_f32(float* c, const uint32_t* a, const uint32_t* b) {
    asm volatile(
        "mma.sync.aligned.m16n8k16.row.col.f32.f16.f16.f32 "
        "{%0,%1,%2,%3}, {%4,%5,%6,%7}, {%8,%9}, {%0,%1,%2,%3};"
        : "+f"(c[0]), "+f"(c[1]), "+f"(c[2]), "+f"(c[3])
        : "r"(a[0]), "r"(a[1]), "r"(a[2]), "r"(a[3]), "r"(b[0]), "r"(b[1]));
}
__device__ __forceinline__ void ldsm4(uint32_t* r, uint32_t addr) {
    asm volatile("ldmatrix.sync.aligned.m8n8.x4.shared.b16 {%0,%1,%2,%3}, [%4];"
        : "=r"(r[0]), "=r"(r[1]), "=r"(r[2]), "=r"(r[3]) : "r"(addr));
}

// ---------------- kernel 0: zero counters ----------------
__global__ void init_kernel() {
    int t = threadIdx.x;
    if (t < 2 * NEXP) { ((int*)g_cnt)[t] = 0; ((int*)g_cur)[t] = 0; }
}

// ---------------- convert weights (fp32 -> fp16 hi), vectorized ----------------
__global__ __launch_bounds__(256) void convw_kernel(const float* __restrict__ w) {
    int i = blockIdx.x * 256 + threadIdx.x;       // one float4 per thread
    float4 v = ((const float4*)w)[i];
    __half2 h0 = __floats2half2_rn(v.x, v.y);
    __half2 h1 = __floats2half2_rn(v.z, v.w);
    ((__half2*)g_wh)[2 * i] = h0;
    ((__half2*)g_wh)[2 * i + 1] = h1;
}

// ---------------- kernel 1: router (fused x hi conversion, float4 path) ----------------
__global__ __launch_bounds__(256) void router_kernel(
    const float* __restrict__ x, const float* __restrict__ rw, const float* __restrict__ rb)
{
    __shared__ float s_rw[NEXP * HDIM];
    for (int i = threadIdx.x; i < NEXP * HDIM; i += 256) s_rw[i] = rw[i];
    __syncthreads();

    int warp = threadIdx.x >> 5, lane = threadIdx.x & 31;
    int tok = (blockIdx.x << 3) + warp;
    const float4* xr = (const float4*)(x + (size_t)tok * HDIM);
    __half2* xh = (__half2*)(g_xh + (size_t)tok * HDIM);

    float acc[NEXP];
#pragma unroll
    for (int e = 0; e < NEXP; e++) acc[e] = 0.f;
#pragma unroll
    for (int i = 0; i < HDIM / 128; i++) {        // 6 iters of float4
        int idx = i * 32 + lane;
        float4 v = xr[idx];
        xh[2 * idx]     = __floats2half2_rn(v.x, v.y);
        xh[2 * idx + 1] = __floats2half2_rn(v.z, v.w);
#pragma unroll
        for (int e = 0; e < NEXP; e++) {
            float4 w4 = ((const float4*)(s_rw + e * HDIM))[idx];
            acc[e] = fmaf(v.x, w4.x, fmaf(v.y, w4.y, fmaf(v.z, w4.z, fmaf(v.w, w4.w, acc[e]))));
        }
    }
#pragma unroll
    for (int e = 0; e < NEXP; e++)
#pragma unroll
        for (int o = 16; o > 0; o >>= 1)
            acc[e] += __shfl_xor_sync(0xffffffffu, acc[e], o);

    if (lane == 0) {
        float s[NEXP];
#pragma unroll
        for (int e = 0; e < NEXP; e++) s[e] = acc[e] + rb[e];
        float m = s[0];
#pragma unroll
        for (int e = 1; e < NEXP; e++) m = fmaxf(m, s[e]);
        float p[NEXP]; float Z = 0.f;
#pragma unroll
        for (int e = 0; e < NEXP; e++) { p[e] = expf(s[e] - m); Z += p[e]; }
        int e0 = 0;
#pragma unroll
        for (int e = 1; e < NEXP; e++) if (p[e] > p[e0]) e0 = e;
        int e1 = (e0 == 0) ? 1 : 0;
#pragma unroll
        for (int e = 0; e < NEXP; e++) if (e != e0 && p[e] > p[e1]) e1 = e;
        float p0 = p[e0] / Z, p1 = p[e1] / Z;
        float inv = 1.f / (p0 + p1 + 1e-9f);
        g_eid[0][tok] = e0; g_wt[0][tok] = p0 * inv;
        g_eid[1][tok] = e1; g_wt[1][tok] = p1 * inv;
        atomicAdd(&g_cnt[0][e0], 1);
        atomicAdd(&g_cnt[1][e1], 1);
    }
}

// ---------------- kernel 2: scan ----------------
__global__ void scan_kernel() {
    if (threadIdx.x == 0 && blockIdx.x == 0) {
        for (int s = 0; s < 2; s++) {
            int o = 0, t = 0;
            for (int e = 0; e < NEXP; e++) {
                g_off[s][e] = o; g_ts[s][e] = t;
                o += g_cnt[s][e];
                t += (g_cnt[s][e] + TM - 1) >> 7;
            }
            g_off[s][NEXP] = o; g_ts[s][NEXP] = t;
        }
    }
}

// ---------------- kernel 3: scatter ----------------
__global__ __launch_bounds__(256) void scatter_kernel() {
    int t = blockIdx.x * 256 + threadIdx.x;
    if (t >= NTOK) return;
#pragma unroll
    for (int s = 0; s < 2; s++) {
        int e = g_eid[s][t];
        int pos = g_off[s][e] + atomicAdd(&g_cur[s][e], 1);
        g_bucket[s][pos] = t;
        g_bw[s][pos] = g_wt[s][t];
    }
}

// ---------------- kernel 4: grouped GEMM, fp16 x fp16 -> f32 accum, 2 CTAs/SM ----------------
template <int SLOT, bool ACC>
__global__ __launch_bounds__(256, 2)
void moe_mma(const float* __restrict__ eb, float* __restrict__ out)
{
    extern __shared__ __align__(128) char smem[];
    const uint32_t sb = (uint32_t)__cvta_generic_to_shared(smem);

    __shared__ int   sMeta[3];
    __shared__ int   sTok[CTM];
    __shared__ float sWgt[CTM];
    __shared__ float sBias[CTN];

    int tid = threadIdx.x;
    int wid = tid >> 5, lane = tid & 31;

    if (tid == 0) {
        int bx = blockIdx.x;
        if (bx >= g_ts[SLOT][NEXP]) sMeta[0] = -1;
        else {
            int e = 0;
            while (g_ts[SLOT][e + 1] <= bx) e++;
            sMeta[0] = e;
            sMeta[1] = g_off[SLOT][e] + ((bx - g_ts[SLOT][e]) << 7);
            sMeta[2] = g_off[SLOT][e + 1];
        }
    }
    __syncthreads();
    int e = sMeta[0];
    if (e < 0) return;
    int m0 = sMeta[1], mEnd = sMeta[2];
    int nBase = blockIdx.y << 7;   // * 128

    if (tid < CTM) {
        int p = m0 + tid;
        int pc = p < mEnd ? p : mEnd - 1;
        sTok[tid] = g_bucket[SLOT][pc];
        sWgt[tid] = g_bw[SLOT][pc];
        sBias[tid] = eb[e * HDIM + nBase + tid];
    }
    __syncthreads();

    // ---- stage loader: 4 cp.async(16B) per thread (Ah, Bh) ----
    int lrow = tid >> 1;                 // 0..127
    int lc0  = (tid & 1) * 2;            // chunk 0 or 2
    size_t gAr = (size_t)sTok[lrow] * HDIM;
    size_t gBr = ((size_t)e * HDIM + nBase + lrow) * HDIM;

    auto load_stage = [&](int kt, int buf) {
        uint32_t sbase = sb + (uint32_t)buf * STAGEB;
        int kc = kt * CTK;
#pragma unroll
        for (int t = 0; t < 2; t++) {
            int c = lc0 + t;
            uint32_t so = (uint32_t)(lrow * ROWB + c * 16);
            cpa16(sbase + 0 * TILEB + so, g_xh + gAr + kc + c * 8);
            cpa16(sbase + 1 * TILEB + so, g_wh + gBr + kc + c * 8);
        }
    };

    load_stage(0, 0); cp_commit();
    load_stage(1, 1); cp_commit();
    load_stage(2, 2); cp_commit();

    int warp_m = wid >> 1, warp_n = wid & 1;
    int r = lane >> 2, q = lane & 3;

    // ldmatrix lane address offsets (bytes within a tile)
    uint32_t aOff = (uint32_t)((warp_m * 32 + (lane & 15)) * ROWB + ((lane >> 4) << 4));
    uint32_t bOff = (uint32_t)((warp_n * 64 + ((lane >> 4) << 3) + (lane & 7)) * ROWB
                               + (((lane >> 3) & 1) << 4));

    float acc[2][8][4];
#pragma unroll
    for (int mt = 0; mt < 2; mt++)
#pragma unroll
        for (int nt = 0; nt < 8; nt++)
#pragma unroll
            for (int i = 0; i < 4; i++) acc[mt][nt][i] = 0.f;

    for (int kt = 0; kt < KT; kt++) {
        int buf = kt & 3;   // NSTG = 4
        if (kt <= KT - 3) cp_wait<2>();
        else if (kt == KT - 2) cp_wait<1>();
        else cp_wait<0>();
        __syncthreads();
        if (kt + 3 < KT) { load_stage(kt + 3, (kt + 3) & 3); cp_commit(); }

        uint32_t tb = sb + (uint32_t)buf * STAGEB;

#pragma unroll
        for (int k16 = 0; k16 < 2; k16++) {
            uint32_t kb = (uint32_t)(k16 * 32);
            uint32_t ah[2][4], bh[8][2];
#pragma unroll
            for (int mt = 0; mt < 2; mt++)
                ldsm4(ah[mt], tb + aOff + (uint32_t)(mt * 16 * ROWB) + kb);
#pragma unroll
            for (int ntp = 0; ntp < 4; ntp++) {
                uint32_t regs[4];
                ldsm4(regs, tb + TILEB + bOff + (uint32_t)(ntp * 16 * ROWB) + kb);
                bh[2 * ntp][0] = regs[0]; bh[2 * ntp][1] = regs[1];
                bh[2 * ntp + 1][0] = regs[2]; bh[2 * ntp + 1][1] = regs[3];
            }
#pragma unroll
            for (int mt = 0; mt < 2; mt++)
#pragma unroll
                for (int nt = 0; nt < 8; nt++)
                    mma16816_f32(acc[mt][nt], ah[mt], bh[nt]);
        }
    }

    // ---- epilogue ----
#pragma unroll
    for (int mt = 0; mt < 2; mt++) {
        int lr0 = warp_m * 32 + mt * 16 + r;
        int lr1 = lr0 + 8;
        bool v0 = (m0 + lr0) < mEnd;
        bool v1 = (m0 + lr1) < mEnd;
        float w0 = sWgt[lr0], w1 = sWgt[lr1];
        float* o0 = out + (size_t)sTok[lr0] * HDIM + nBase;
        float* o1 = out + (size_t)sTok[lr1] * HDIM + nBase;
#pragma unroll
        for (int nt = 0; nt < 8; nt++) {
            int lc = warp_n * 64 + nt * 8 + 2 * q;
            float bx = sBias[lc], by = sBias[lc + 1];
            if (v0) {
                float2 v;
                v.x = w0 * (acc[mt][nt][0] + bx);
                v.y = w0 * (acc[mt][nt][1] + by);
                float2* dst = (float2*)(o0 + lc);
                if (ACC) { float2 o = *dst; o.x += v.x; o.y += v.y; *dst = o; }
                else *dst = v;
            }
            if (v1) {
                float2 v;
                v.x = w1 * (acc[mt][nt][2] + bx);
                v.y = w1 * (acc[mt][nt][3] + by);
                float2* dst = (float2*)(o1 + lc);
                if (ACC) { float2 o = *dst; o.x += v.x; o.y += v.y; *dst = o; }
                else *dst = v;
            }
        }
    }
}

// ---------------- launch ----------------
extern "C" void kernel_launch(void* const* d_in, const int* in_sizes, int n_in,
                              void* d_out, int out_size)
{
    const float* x  = (const float*)d_in[0];
    const float* rw = (const float*)d_in[1];
    const float* rb = (const float*)d_in[2];
    const float* ew = (const float*)d_in[3];
    const float* eb = (const float*)d_in[4];
    float* out = (float*)d_out;
    (void)in_sizes; (void)n_in; (void)out_size;

    cudaFuncSetAttribute(moe_mma<0, false>, cudaFuncAttributeMaxDynamicSharedMemorySize, SMEM_BYTES);
    cudaFuncSetAttribute(moe_mma<1, true >, cudaFuncAttributeMaxDynamicSharedMemorySize, SMEM_BYTES);

    init_kernel<<<1, 32>>>();
    convw_kernel<<<NEXP * HDIM * HDIM / 1024, 256>>>(ew);
    router_kernel<<<NTOK / 8, 256>>>(x, rw, rb);
    scan_kernel<<<1, 32>>>();
    scatter_kernel<<<NTOK / 256, 256>>>();
    moe_mma<0, false><<<dim3(MAXTILES, HDIM / CTN), 256, SMEM_BYTES>>>(eb, out);
    moe_mma<1, true ><<<dim3(MAXTILES, HDIM / CTN), 256, SMEM_BYTES>>>(eb, out);
}